// round 6
// baseline (speedup 1.0000x reference)
#include <cuda_runtime.h>
#include <cuda_fp16.h>

#define BB 8
#define NN 2048
#define FIN 256
#define FOUT 64
#define LALPHA 0.2f
#define EBIAS 8.0f
#define SPLIT 16
#define SPLITJ 4

// ---- scratch (device globals; no allocation) ----
__device__ float  g_WhL[BB * NN * FOUT];           // Wh*level, then *inv (4 MB)
__device__ float  g_f1[BB * NN];
__device__ float  g_f2[BB * NN];
__device__ float  g_part[SPLIT * BB * NN];
__device__ __half g_expe[(size_t)BB * NN * NN];    // exp(e-8) fp16, masked->0 (67 MB)
__device__ float  g_pout[(size_t)SPLITJ * BB * NN * FOUT];  // j-split partials (16 MB)

// =====================================================================
// Kernel A: Wh = h@W, WhL = Wh*level, f1 = Wh@a1, f2 = Wh@a2
// =====================================================================
__global__ __launch_bounds__(256) void k_proj(const float* __restrict__ h,
                                              const float* __restrict__ W,
                                              const float* __restrict__ a,
                                              const float* __restrict__ level)
{
    __shared__ float sh_h[32 * FIN];
    __shared__ float red1[8][4][2];
    __shared__ float red2[8][4][2];

    const int t = threadIdx.x;
    const int row0 = blockIdx.x * 32;

    const float4* hg = (const float4*)(h + (size_t)row0 * FIN);
    float4* hs = (float4*)sh_h;
#pragma unroll
    for (int k = 0; k < 8; ++k) hs[t + k * 256] = hg[t + k * 256];
    __syncthreads();

    const int o = t & 63;
    const int g = t >> 6;
    const float a1o = a[o];
    const float a2o = a[FOUT + o];

    float acc[8] = {0.f, 0.f, 0.f, 0.f, 0.f, 0.f, 0.f, 0.f};

#pragma unroll 4
    for (int f4 = 0; f4 < FIN / 4; ++f4) {
        const float w0 = __ldg(&W[(f4 * 4 + 0) * FOUT + o]);
        const float w1 = __ldg(&W[(f4 * 4 + 1) * FOUT + o]);
        const float w2 = __ldg(&W[(f4 * 4 + 2) * FOUT + o]);
        const float w3 = __ldg(&W[(f4 * 4 + 3) * FOUT + o]);
#pragma unroll
        for (int rr = 0; rr < 8; ++rr) {
            const float4 hv = *(const float4*)&sh_h[(g * 8 + rr) * FIN + f4 * 4];
            acc[rr] = fmaf(hv.x, w0, acc[rr]);
            acc[rr] = fmaf(hv.y, w1, acc[rr]);
            acc[rr] = fmaf(hv.z, w2, acc[rr]);
            acc[rr] = fmaf(hv.w, w3, acc[rr]);
        }
    }

    const int lane = t & 31;
    const int half = (t >> 5) & 1;
#pragma unroll
    for (int rr = 0; rr < 8; ++rr) {
        const int row = row0 + g * 8 + rr;
        const float lev = __ldg(&level[row]);
        g_WhL[(size_t)row * FOUT + o] = acc[rr] * lev;
        float v1 = acc[rr] * a1o;
        float v2 = acc[rr] * a2o;
#pragma unroll
        for (int off = 16; off; off >>= 1) {
            v1 += __shfl_down_sync(0xffffffffu, v1, off);
            v2 += __shfl_down_sync(0xffffffffu, v2, off);
        }
        if (lane == 0) { red1[rr][g][half] = v1; red2[rr][g][half] = v2; }
    }
    __syncthreads();
    if (t < 32) {
        const int g2 = t >> 3, rr2 = t & 7;
        const int row = row0 + g2 * 8 + rr2;
        g_f1[row] = red1[rr2][g2][0] + red1[rr2][g2][1];
        g_f2[row] = red2[rr2][g2][0] + red2[rr2][g2][1];
    }
}

// =====================================================================
// Kernel B: expe = fp16(exp(e-8)) (0 where masked) + partial column sums.
// Each thread owns TWO adjacent columns: int2/float2 loads, half2 stores.
// grid (NN/512, BB, SPLIT) x 256 threads.
// =====================================================================
__global__ __launch_bounds__(256) void k_colsum(const int* __restrict__ adj,
                                                const float* __restrict__ nt)
{
    const int j = (blockIdx.x * 256 + threadIdx.x) * 2;
    const int b = blockIdx.y;
    const int i0 = blockIdx.z * (NN / SPLIT);

    const float f2a = __ldg(&g_f2[b * NN + j]);
    const float f2b = __ldg(&g_f2[b * NN + j + 1]);
    const float* f1p = g_f1 + b * NN + i0;
    size_t base = ((size_t)(b * NN + i0)) * NN + j;

    float s0 = 0.f, s1 = 0.f;
#pragma unroll 4
    for (int ii = 0; ii < NN / SPLIT; ++ii) {
        const int2   av  = *(const int2*)(adj + base);
        const float2 ntv = *(const float2*)(nt + base);
        const float  f1i = __ldg(&f1p[ii]);
        float pv0 = 0.f, pv1 = 0.f;
        if (av.x > 0) {
            const float x = f1i + f2a;
            pv0 = __expf((x > 0.f ? x : LALPHA * x) * ntv.x - EBIAS);
        }
        if (av.y > 0) {
            const float x = f1i + f2b;
            pv1 = __expf((x > 0.f ? x : LALPHA * x) * ntv.y - EBIAS);
        }
        const __half2 hv = __floats2half2_rn(pv0, pv1);
        *(__half2*)(g_expe + base) = hv;
        const float2 rv = __half22float2(hv);   // accumulate rounded values
        s0 += rv.x; s1 += rv.y;
        base += NN;
    }
    float* pp = g_part + ((size_t)blockIdx.z * BB + b) * NN + j;
    pp[0] = s0; pp[1] = s1;
}

// =====================================================================
// Combine partials -> inv, and scale WhL by inv (fused).
// Block handles 16 columns; grid = BB*NN/16 = 1024 blocks.
// =====================================================================
__global__ __launch_bounds__(256) void k_comb()
{
    __shared__ float sinv[16];
    const int t = threadIdx.x;
    const int col0 = blockIdx.x * 16;

    if (t < 16) {
        const int c = col0 + t;
        float s = 0.f;
#pragma unroll
        for (int k = 0; k < SPLIT; ++k) s += g_part[k * (BB * NN) + c];
        sinv[t] = 1.0f / s;
    }
    __syncthreads();

    const int c  = col0 + (t >> 4);
    const int o4 = t & 15;
    const float inv = sinv[t >> 4];
    float4* w = (float4*)g_WhL + (size_t)c * 16 + o4;
    float4 v = *w;
    v.x *= inv; v.y *= inv; v.z *= inv; v.w *= inv;
    *w = v;
}

// =====================================================================
// Kernel C: partial h_prime over a j-slice (P from fp16 g_expe).
// grid (32 i-tiles, B, SPLITJ); 64 i x 64 o per block, FFMA2 inner loop.
// =====================================================================
__global__ __launch_bounds__(256) void k_attn()
{
    __shared__ float sh_w[64 * 64];   // scaled WhL chunk [jj][o]
    __shared__ float sh_p[64 * 65];   // P transposed [jj][il], padded

    const int t = threadIdx.x;
    const int i0 = blockIdx.x * 64;
    const int b  = blockIdx.y;
    const int js = blockIdx.z;

    const int jj = t & 63;
    const int ig = t >> 6;            // 4 groups x 16 rows
    const int il = t & 31;
    const int oc = (t >> 5) * 8;

    unsigned long long acc0[4] = {0ull, 0ull, 0ull, 0ull};
    unsigned long long acc1[4] = {0ull, 0ull, 0ull, 0ull};

    for (int jt = 0; jt < NN / SPLITJ / 64; ++jt) {
        const int j0 = js * (NN / SPLITJ) + jt * 64;

        // --- stage scaled WhL chunk (contiguous float4) ---
        {
            const float4* src = (const float4*)(g_WhL + ((size_t)(b * NN + j0)) * FOUT);
            float4* dst = (float4*)sh_w;
#pragma unroll
            for (int k = 0; k < 4; ++k) dst[t + k * 256] = src[t + k * 256];
        }

        // --- stage P tile transposed: fp16 gmem -> fp32 smem ---
        {
            const __half* ep = g_expe + ((size_t)(b * NN + i0 + ig * 16)) * NN + j0 + jj;
#pragma unroll
            for (int r = 0; r < 16; ++r)
                sh_p[jj * 65 + ig * 16 + r] = __half2float(__ldg(ep + (size_t)r * NN));
        }
        __syncthreads();

        // --- acc[i][o] += P[i][j] * WhL'[j][o]  (packed f32x2) ---
#pragma unroll 8
        for (int j = 0; j < 64; ++j) {
            const float p0 = sh_p[j * 65 + il];
            const float p1 = sh_p[j * 65 + il + 32];
            unsigned long long pp0, pp1;
            asm("mov.b64 %0, {%1, %1};" : "=l"(pp0) : "f"(p0));
            asm("mov.b64 %0, {%1, %1};" : "=l"(pp1) : "f"(p1));
            const ulonglong2* wv = (const ulonglong2*)&sh_w[j * 64 + oc];
            const ulonglong2 wA = wv[0];
            const ulonglong2 wB = wv[1];
            asm("fma.rn.f32x2 %0, %1, %2, %0;" : "+l"(acc0[0]) : "l"(pp0), "l"(wA.x));
            asm("fma.rn.f32x2 %0, %1, %2, %0;" : "+l"(acc0[1]) : "l"(pp0), "l"(wA.y));
            asm("fma.rn.f32x2 %0, %1, %2, %0;" : "+l"(acc0[2]) : "l"(pp0), "l"(wB.x));
            asm("fma.rn.f32x2 %0, %1, %2, %0;" : "+l"(acc0[3]) : "l"(pp0), "l"(wB.y));
            asm("fma.rn.f32x2 %0, %1, %2, %0;" : "+l"(acc1[0]) : "l"(pp1), "l"(wA.x));
            asm("fma.rn.f32x2 %0, %1, %2, %0;" : "+l"(acc1[1]) : "l"(pp1), "l"(wA.y));
            asm("fma.rn.f32x2 %0, %1, %2, %0;" : "+l"(acc1[2]) : "l"(pp1), "l"(wB.x));
            asm("fma.rn.f32x2 %0, %1, %2, %0;" : "+l"(acc1[3]) : "l"(pp1), "l"(wB.y));
        }
        __syncthreads();
    }

    // --- store partials (no relu yet) ---
    float r0[8], r1[8];
#pragma unroll
    for (int k = 0; k < 4; ++k) {
        asm("mov.b64 {%0, %1}, %2;" : "=f"(r0[2*k]), "=f"(r0[2*k+1]) : "l"(acc0[k]));
        asm("mov.b64 {%0, %1}, %2;" : "=f"(r1[2*k]), "=f"(r1[2*k+1]) : "l"(acc1[k]));
    }
    float* op0 = g_pout + (((size_t)js * BB + b) * NN + i0 + il) * FOUT + oc;
    float* op1 = op0 + (size_t)32 * FOUT;
    ((float4*)op0)[0] = make_float4(r0[0], r0[1], r0[2], r0[3]);
    ((float4*)op0)[1] = make_float4(r0[4], r0[5], r0[6], r0[7]);
    ((float4*)op1)[0] = make_float4(r1[0], r1[1], r1[2], r1[3]);
    ((float4*)op1)[1] = make_float4(r1[4], r1[5], r1[6], r1[7]);
}

// =====================================================================
// Combine j-split partials + relu -> out
// =====================================================================
__global__ __launch_bounds__(256) void k_out(float* __restrict__ out)
{
    const int i4 = blockIdx.x * 256 + threadIdx.x;   // float4 index
    const size_t stride4 = (size_t)BB * NN * FOUT / 4;
    float4 s = ((const float4*)g_pout)[i4];
#pragma unroll
    for (int k = 1; k < SPLITJ; ++k) {
        const float4 v = ((const float4*)g_pout)[k * stride4 + i4];
        s.x += v.x; s.y += v.y; s.z += v.z; s.w += v.w;
    }
    s.x = fmaxf(s.x, 0.f); s.y = fmaxf(s.y, 0.f);
    s.z = fmaxf(s.z, 0.f); s.w = fmaxf(s.w, 0.f);
    ((float4*)out)[i4] = s;
}

// =====================================================================
extern "C" void kernel_launch(void* const* d_in, const int* in_sizes, int n_in,
                              void* d_out, int out_size)
{
    const float* h     = (const float*)d_in[0];
    const int*   adj   = (const int*)  d_in[1];
    const float* level = (const float*)d_in[2];
    const float* nt    = (const float*)d_in[3];
    const float* W     = (const float*)d_in[4];
    const float* a     = (const float*)d_in[5];
    float* out = (float*)d_out;

    k_proj<<<(BB * NN) / 32, 256>>>(h, W, a, level);
    dim3 gb(NN / 512, BB, SPLIT);
    k_colsum<<<gb, 256>>>(adj, nt);
    k_comb<<<(BB * NN) / 16, 256>>>();
    dim3 ga(NN / 64, BB, SPLITJ);
    k_attn<<<ga, 256>>>();
    k_out<<<(BB * NN * FOUT / 4) / 256, 256>>>(out);
}

// round 7
// speedup vs baseline: 1.9362x; 1.9362x over previous
#include <cuda_runtime.h>
#include <cuda_fp16.h>
#include <cstdint>

#define BB 8
#define NN 2048
#define FIN 256
#define FOUT 64
#define LALPHA 0.2f
#define EBIAS 8.0f
#define SPLIT 32

// ---- scratch (device globals; no allocation) ----
__device__ float  g_WhL[BB * NN * FOUT];           // Wh*level fp32 (4 MB)
__device__ __half g_WhLh[BB * NN * FOUT];          // scaled fp16 (2 MB)
__device__ float  g_f1[BB * NN];
__device__ float  g_f2[BB * NN];
__device__ float  g_part[SPLIT * BB * NN];
__device__ __half g_expe[(size_t)BB * NN * NN];    // exp(e-8) fp16, masked->0 (67 MB)

static __device__ __forceinline__ uint32_t smem_u32(const void* p) {
    return (uint32_t)__cvta_generic_to_shared(p);
}

// =====================================================================
// Kernel A: Wh = h@W, WhL = Wh*level, f1 = Wh@a1, f2 = Wh@a2
// =====================================================================
__global__ __launch_bounds__(256) void k_proj(const float* __restrict__ h,
                                              const float* __restrict__ W,
                                              const float* __restrict__ a,
                                              const float* __restrict__ level)
{
    __shared__ float sh_h[32 * FIN];
    __shared__ float red1[8][4][2];
    __shared__ float red2[8][4][2];

    const int t = threadIdx.x;
    const int row0 = blockIdx.x * 32;

    const float4* hg = (const float4*)(h + (size_t)row0 * FIN);
    float4* hs = (float4*)sh_h;
#pragma unroll
    for (int k = 0; k < 8; ++k) hs[t + k * 256] = hg[t + k * 256];
    __syncthreads();

    const int o = t & 63;
    const int g = t >> 6;
    const float a1o = a[o];
    const float a2o = a[FOUT + o];

    float acc[8] = {0.f, 0.f, 0.f, 0.f, 0.f, 0.f, 0.f, 0.f};

#pragma unroll 4
    for (int f4 = 0; f4 < FIN / 4; ++f4) {
        const float w0 = __ldg(&W[(f4 * 4 + 0) * FOUT + o]);
        const float w1 = __ldg(&W[(f4 * 4 + 1) * FOUT + o]);
        const float w2 = __ldg(&W[(f4 * 4 + 2) * FOUT + o]);
        const float w3 = __ldg(&W[(f4 * 4 + 3) * FOUT + o]);
#pragma unroll
        for (int rr = 0; rr < 8; ++rr) {
            const float4 hv = *(const float4*)&sh_h[(g * 8 + rr) * FIN + f4 * 4];
            acc[rr] = fmaf(hv.x, w0, acc[rr]);
            acc[rr] = fmaf(hv.y, w1, acc[rr]);
            acc[rr] = fmaf(hv.z, w2, acc[rr]);
            acc[rr] = fmaf(hv.w, w3, acc[rr]);
        }
    }

    const int lane = t & 31;
    const int half = (t >> 5) & 1;
#pragma unroll
    for (int rr = 0; rr < 8; ++rr) {
        const int row = row0 + g * 8 + rr;
        const float lev = __ldg(&level[row]);
        g_WhL[(size_t)row * FOUT + o] = acc[rr] * lev;
        float v1 = acc[rr] * a1o;
        float v2 = acc[rr] * a2o;
#pragma unroll
        for (int off = 16; off; off >>= 1) {
            v1 += __shfl_down_sync(0xffffffffu, v1, off);
            v2 += __shfl_down_sync(0xffffffffu, v2, off);
        }
        if (lane == 0) { red1[rr][g][half] = v1; red2[rr][g][half] = v2; }
    }
    __syncthreads();
    if (t < 32) {
        const int g2 = t >> 3, rr2 = t & 7;
        const int row = row0 + g2 * 8 + rr2;
        g_f1[row] = red1[rr2][g2][0] + red1[rr2][g2][1];
        g_f2[row] = red2[rr2][g2][0] + red2[rr2][g2][1];
    }
}

// =====================================================================
// Kernel B: expe = fp16(exp(e-8)) (0 where masked) + partial column sums.
// 4 columns/thread: int4/float4 loads, 8B fp16 store.
// grid (NN/1024, BB, SPLIT) x 256 threads; 64 rows per block.
// =====================================================================
__global__ __launch_bounds__(256) void k_colsum(const int* __restrict__ adj,
                                                const float* __restrict__ nt)
{
    const int j = (blockIdx.x * 256 + threadIdx.x) * 4;
    const int b = blockIdx.y;
    const int i0 = blockIdx.z * (NN / SPLIT);

    const float4 f2v = *(const float4*)(g_f2 + b * NN + j);
    const float* f1p = g_f1 + b * NN + i0;
    size_t base = ((size_t)(b * NN + i0)) * NN + j;

    float s0 = 0.f, s1 = 0.f, s2 = 0.f, s3 = 0.f;
#pragma unroll 4
    for (int ii = 0; ii < NN / SPLIT; ++ii) {
        const int4   av  = *(const int4*)(adj + base);
        const float4 ntv = *(const float4*)(nt + base);
        const float  f1i = __ldg(&f1p[ii]);
        float p0 = 0.f, p1 = 0.f, p2 = 0.f, p3 = 0.f;
        if (av.x > 0) { const float x = f1i + f2v.x; p0 = __expf((x > 0.f ? x : LALPHA * x) * ntv.x - EBIAS); }
        if (av.y > 0) { const float x = f1i + f2v.y; p1 = __expf((x > 0.f ? x : LALPHA * x) * ntv.y - EBIAS); }
        if (av.z > 0) { const float x = f1i + f2v.z; p2 = __expf((x > 0.f ? x : LALPHA * x) * ntv.z - EBIAS); }
        if (av.w > 0) { const float x = f1i + f2v.w; p3 = __expf((x > 0.f ? x : LALPHA * x) * ntv.w - EBIAS); }
        const __half2 h01 = __floats2half2_rn(p0, p1);
        const __half2 h23 = __floats2half2_rn(p2, p3);
        uint2 st;
        st.x = *(const unsigned int*)&h01;
        st.y = *(const unsigned int*)&h23;
        *(uint2*)(g_expe + base) = st;
        const float2 r01 = __half22float2(h01);   // accumulate rounded values
        const float2 r23 = __half22float2(h23);
        s0 += r01.x; s1 += r01.y; s2 += r23.x; s3 += r23.y;
        base += NN;
    }
    float* pp = g_part + ((size_t)blockIdx.z * BB + b) * NN + j;
    *(float4*)pp = make_float4(s0, s1, s2, s3);
}

// =====================================================================
// Combine partials -> inv; WhLh = fp16(WhL * inv). 16 cols per block.
// =====================================================================
__global__ __launch_bounds__(256) void k_comb()
{
    __shared__ float sinv[16];
    const int t = threadIdx.x;
    const int col0 = blockIdx.x * 16;

    if (t < 16) {
        const int c = col0 + t;
        float s = 0.f;
#pragma unroll
        for (int k = 0; k < SPLIT; ++k) s += g_part[k * (BB * NN) + c];
        sinv[t] = 1.0f / s;
    }
    __syncthreads();

    const int cc = t >> 4;             // 0..15 column within block
    const int o4 = t & 15;             // float4 index within column
    const float inv = sinv[cc];
    const float4 v = ((const float4*)g_WhL)[(size_t)(col0 + cc) * 16 + o4];
    const __half2 h0 = __floats2half2_rn(v.x * inv, v.y * inv);
    const __half2 h1 = __floats2half2_rn(v.z * inv, v.w * inv);
    uint2 u;
    u.x = *(const unsigned int*)&h0;
    u.y = *(const unsigned int*)&h1;
    ((uint2*)g_WhLh)[(size_t)(col0 + cc) * 16 + o4] = u;
}

// =====================================================================
// Kernel C: out[b,i,:] = relu( P[b,i,:] @ WhLh[b,:,:] ) via HMMA.
// Block: 64 i x 64 o, K=2048 swept in 64-chunks, double-buffered smem.
// 8 warps: warp (wr,wc) computes i rows [wr*16,+16) x o cols [wc*32,+32).
// grid (NN/64, BB) = 256 blocks x 256 threads.
// =====================================================================
#define PITCH 72   // halves; 144B row pitch -> conflict-free ldmatrix/STS

__global__ __launch_bounds__(256) void k_attn(float* __restrict__ out)
{
    __shared__ __half Ps[2][64 * PITCH];
    __shared__ __half Ws[2][64 * PITCH];

    const int t = threadIdx.x;
    const int lane = t & 31;
    const int warp = t >> 5;
    const int wr = warp >> 1;          // 0..3
    const int wc = warp & 1;           // 0..1
    const int b  = blockIdx.y;
    const int i0 = blockIdx.x * 64;

    // gmem->smem staging: 512 chunks of 16B (64 rows x 8); ids t and t+256
    const int r0 = t >> 3, c0 = t & 7;
    const int r1 = r0 + 32;
    const __half* Pg = g_expe + ((size_t)(b * NN + i0)) * NN;
    const __half* Wg = g_WhLh + (size_t)b * NN * FOUT;

    float d[4][4];
#pragma unroll
    for (int n = 0; n < 4; ++n)
#pragma unroll
        for (int k = 0; k < 4; ++k) d[n][k] = 0.f;

    // ldmatrix source addresses (byte offsets into smem)
    const uint32_t aBase = smem_u32(&Ps[0][(wr * 16 + (lane & 15)) * PITCH + (lane >> 4) * 8]);
    const uint32_t bBase = smem_u32(&Ws[0][(lane & 15) * PITCH + wc * 32 + (lane >> 4) * 8]);
    const uint32_t bufStride = 64 * PITCH * sizeof(__half);

    // ---- preload chunk 0 ----
    uint4 pa = *(const uint4*)(Pg + (size_t)r0 * NN + c0 * 8);
    uint4 pb = *(const uint4*)(Pg + (size_t)r1 * NN + c0 * 8);
    uint4 wa = *(const uint4*)(Wg + (size_t)r0 * FOUT + c0 * 8);
    uint4 wb = *(const uint4*)(Wg + (size_t)r1 * FOUT + c0 * 8);
    *(uint4*)&Ps[0][r0 * PITCH + c0 * 8] = pa;
    *(uint4*)&Ps[0][r1 * PITCH + c0 * 8] = pb;
    *(uint4*)&Ws[0][r0 * PITCH + c0 * 8] = wa;
    *(uint4*)&Ws[0][r1 * PITCH + c0 * 8] = wb;
    __syncthreads();

    for (int ck = 0; ck < NN / 64; ++ck) {
        const int buf = ck & 1;

        // prefetch next chunk into registers
        if (ck < NN / 64 - 1) {
            const int k0 = (ck + 1) * 64;
            pa = *(const uint4*)(Pg + (size_t)r0 * NN + k0 + c0 * 8);
            pb = *(const uint4*)(Pg + (size_t)r1 * NN + k0 + c0 * 8);
            wa = *(const uint4*)(Wg + (size_t)(k0 + r0) * FOUT + c0 * 8);
            wb = *(const uint4*)(Wg + (size_t)(k0 + r1) * FOUT + c0 * 8);
        }

        // ---- MMA on current buffer ----
        const uint32_t aB = aBase + buf * bufStride;
        const uint32_t bB = bBase + buf * bufStride;
#pragma unroll
        for (int ks = 0; ks < 4; ++ks) {
            uint32_t a0, a1, a2, a3;
            asm volatile("ldmatrix.sync.aligned.m8n8.x4.shared.b16 {%0,%1,%2,%3}, [%4];"
                         : "=r"(a0), "=r"(a1), "=r"(a2), "=r"(a3)
                         : "r"(aB + ks * 16 * 2));
#pragma unroll
            for (int np = 0; np < 2; ++np) {
                uint32_t b0, b1, b2, b3;
                asm volatile("ldmatrix.sync.aligned.m8n8.x4.trans.shared.b16 {%0,%1,%2,%3}, [%4];"
                             : "=r"(b0), "=r"(b1), "=r"(b2), "=r"(b3)
                             : "r"(bB + (ks * 16 * PITCH + np * 16) * 2));
                asm volatile("mma.sync.aligned.m16n8k16.row.col.f32.f16.f16.f32 "
                             "{%0,%1,%2,%3}, {%4,%5,%6,%7}, {%8,%9}, {%0,%1,%2,%3};"
                             : "+f"(d[np*2][0]), "+f"(d[np*2][1]), "+f"(d[np*2][2]), "+f"(d[np*2][3])
                             : "r"(a0), "r"(a1), "r"(a2), "r"(a3), "r"(b0), "r"(b1));
                asm volatile("mma.sync.aligned.m16n8k16.row.col.f32.f16.f16.f32 "
                             "{%0,%1,%2,%3}, {%4,%5,%6,%7}, {%8,%9}, {%0,%1,%2,%3};"
                             : "+f"(d[np*2+1][0]), "+f"(d[np*2+1][1]), "+f"(d[np*2+1][2]), "+f"(d[np*2+1][3])
                             : "r"(a0), "r"(a1), "r"(a2), "r"(a3), "r"(b2), "r"(b3));
            }
        }

        // stage prefetched chunk into the other buffer
        if (ck < NN / 64 - 1) {
            const int nb = buf ^ 1;
            *(uint4*)&Ps[nb][r0 * PITCH + c0 * 8] = pa;
            *(uint4*)&Ps[nb][r1 * PITCH + c0 * 8] = pb;
            *(uint4*)&Ws[nb][r0 * PITCH + c0 * 8] = wa;
            *(uint4*)&Ws[nb][r1 * PITCH + c0 * 8] = wb;
            __syncthreads();
        }
    }

    // ---- epilogue: relu + store ----
    const int orow = i0 + wr * 16 + (lane >> 2);
    const int ocol = wc * 32 + (lane & 3) * 2;
    float* obase = out + ((size_t)(b * NN + orow)) * FOUT + ocol;
#pragma unroll
    for (int nt4 = 0; nt4 < 4; ++nt4) {
        float2 v0, v1;
        v0.x = fmaxf(d[nt4][0], 0.f); v0.y = fmaxf(d[nt4][1], 0.f);
        v1.x = fmaxf(d[nt4][2], 0.f); v1.y = fmaxf(d[nt4][3], 0.f);
        *(float2*)(obase + nt4 * 8) = v0;
        *(float2*)(obase + (size_t)8 * FOUT + nt4 * 8) = v1;
    }
}

// =====================================================================
extern "C" void kernel_launch(void* const* d_in, const int* in_sizes, int n_in,
                              void* d_out, int out_size)
{
    const float* h     = (const float*)d_in[0];
    const int*   adj   = (const int*)  d_in[1];
    const float* level = (const float*)d_in[2];
    const float* nt    = (const float*)d_in[3];
    const float* W     = (const float*)d_in[4];
    const float* a     = (const float*)d_in[5];
    float* out = (float*)d_out;

    k_proj<<<(BB * NN) / 32, 256>>>(h, W, a, level);
    dim3 gb(NN / 1024, BB, SPLIT);
    k_colsum<<<gb, 256>>>(adj, nt);
    k_comb<<<(BB * NN) / 16, 256>>>();
    dim3 ga(NN / 64, BB);
    k_attn<<<ga, 256>>>(out);
}